// round 10
// baseline (speedup 1.0000x reference)
#include <cuda_runtime.h>
#include <cuda_bf16.h>
#include <cstdint>

// WarpedNonlinearity (math validated R1; bf16-split pipeline validated R8/R9 @4e-6):
//   4*y = silu(x) + silu(x*Su)*Sd + Su*( silu(Su^T*x) + silu((Su^T*x)*Su)*Sd )
// R10: single 8-warp chain per CTA (2 images), slim 97KB smem -> TWO CTAs PER SM.
// E2 streams first output part to global; E6 accumulates branch2 via global RMW.

#define SM_TPTR  0
#define SM_MBAR  16
#define SM_S64   64
#define SM_BUH   1024
#define SM_BUL   9216
#define SM_BDH   17408
#define SM_BDL   25600
#define SM_S0H   33792      // x -> a11        (hi)
#define SM_S0L   50176
#define SM_S1H   66560      // xT -> a01 -> x10 -> W^T  (hi)
#define SM_S1L   82944
#define SM_TOTAL 99328

#define IDESC_BF16 0x8100490u  // f32 acc | aBF16 | bBF16 | (64/8)<<17 | (128/16)<<24

static constexpr uint64_t DESC_SW128 =
    (uint64_t(2) << 61) | (uint64_t(1) << 46) | (uint64_t(64) << 32) | (uint64_t(1) << 16);

__device__ __forceinline__ float silu_f(float v) {
    return __fdividef(v, 1.0f + __expf(-v));
}

#if defined(__CUDA_ARCH_FEAT_SM103_ALL)
__device__ __forceinline__ uint32_t smem_u32(const void* p) {
    uint32_t a;
    asm("{ .reg .u64 t; cvta.to.shared.u64 t, %1; cvt.u32.u64 %0, t; }" : "=r"(a) : "l"(p));
    return a;
}
__device__ __forceinline__ uint32_t elect1() {
    uint32_t r;
    asm volatile("{ .reg .pred p; elect.sync _|p, 0xFFFFFFFF; selp.b32 %0,1,0,p; }" : "=r"(r));
    return r;
}
// bf16 K-major SW128, K=64 (=128B row, single atom column)
__device__ __forceinline__ uint32_t amap16(uint32_t r, uint32_t c) {
    return (r * 128u + 2u * c) ^ ((r & 7u) << 4);
}
// packed split: {hi2, lo2} for pair (v0 low half, v1 high half)
__device__ __forceinline__ void bsplit2(float v0, float v1, uint32_t& hi2, uint32_t& lo2) {
    asm("cvt.rn.bf16x2.f32 %0, %1, %2;" : "=r"(hi2) : "f"(v1), "f"(v0));
    float h0 = __uint_as_float(hi2 << 16);
    float h1 = __uint_as_float(hi2 & 0xffff0000u);
    float l0 = v0 - h0, l1 = v1 - h1;
    asm("cvt.rn.bf16x2.f32 %0, %1, %2;" : "=r"(lo2) : "f"(l1), "f"(l0));
}
__device__ __forceinline__ float bjoin2(uint32_t h2, uint32_t l2, int hi_half) {
    uint32_t hb = hi_half ? (h2 & 0xffff0000u) : (h2 << 16);
    uint32_t lb = hi_half ? (l2 & 0xffff0000u) : (l2 << 16);
    return __uint_as_float(hb) + __uint_as_float(lb);
}

#define MBARRIER_INIT(a, n) \
    asm volatile("mbarrier.init.shared.b64 [%0], %1;" :: "r"((uint32_t)(a)), "r"((uint32_t)(n)) : "memory")
#define MBARRIER_INVAL(a) \
    asm volatile("mbarrier.inval.shared.b64 [%0];" :: "r"((uint32_t)(a)) : "memory")
#define MBARRIER_WAIT_PARITY(mb, par) do { \
    uint32_t _m = (uint32_t)(mb), _p = (uint32_t)(par), _d; \
    asm volatile("{\n\t.reg .pred p;\n\t" \
        "mbarrier.try_wait.parity.acquire.cta.shared::cta.b64 p, [%1], %2;\n\t" \
        "selp.b32 %0, 1, 0, p;\n\t}" : "=r"(_d) : "r"(_m), "r"(_p) : "memory"); \
    if (!_d) { \
        asm volatile("{\n\t.reg .pred P1;\n\t" \
            "WL_%=:\n\t" \
            "mbarrier.try_wait.parity.acquire.cta.shared::cta.b64 P1, [%0], %1, 0x989680;\n\t" \
            "@P1 bra.uni WD_%=;\n\tbra.uni WL_%=;\n\tWD_%=:\n\t}" \
            :: "r"(_m), "r"(_p) : "memory"); \
    } } while (0)

#define TCGEN05_ALLOC(a, n) \
    asm volatile("tcgen05.alloc.cta_group::1.sync.aligned.shared::cta.b32 [%0], %1;" \
                 :: "r"((uint32_t)(a)), "r"((uint32_t)(n)) : "memory")
#define TCGEN05_DEALLOC(t, n) \
    asm volatile("tcgen05.dealloc.cta_group::1.sync.aligned.b32 %0, %1;" :: "r"(t), "r"((uint32_t)(n)))
#define TCGEN05_RELINQ() \
    asm volatile("tcgen05.relinquish_alloc_permit.cta_group::1.sync.aligned;")
#define TCGEN05_COMMIT(mb) \
    asm volatile("tcgen05.commit.cta_group::1.mbarrier::arrive::one.shared::cluster.b64 [%0];" \
                 :: "r"((uint32_t)(mb)) : "memory")
#define TCGEN05_WAIT_LD()  asm volatile("tcgen05.wait::ld.sync.aligned;" ::: "memory")
#define TCGEN05_FENCE_BEFORE() asm volatile("tcgen05.fence::before_thread_sync;" ::: "memory")
#define TCGEN05_FENCE_AFTER()  asm volatile("tcgen05.fence::after_thread_sync;" ::: "memory")
#define FENCE_PROXY_ASYNC() asm volatile("fence.proxy.async.shared::cta;" ::: "memory")
#define HALF_BAR() asm volatile("bar.sync 1, 128;" ::: "memory")

#define LDTM_X32(r, addr) \
    asm volatile("tcgen05.ld.sync.aligned.32x32b.x32.b32 " \
        "{%0, %1, %2, %3, %4, %5, %6, %7, %8, %9, %10, %11, %12, %13, %14, %15, " \
        " %16, %17, %18, %19, %20, %21, %22, %23, %24, %25, %26, %27, %28, %29, %30, %31}, [%32];" \
        : "=r"((r)[0]),  "=r"((r)[1]),  "=r"((r)[2]),  "=r"((r)[3]), \
          "=r"((r)[4]),  "=r"((r)[5]),  "=r"((r)[6]),  "=r"((r)[7]), \
          "=r"((r)[8]),  "=r"((r)[9]),  "=r"((r)[10]), "=r"((r)[11]), \
          "=r"((r)[12]), "=r"((r)[13]), "=r"((r)[14]), "=r"((r)[15]), \
          "=r"((r)[16]), "=r"((r)[17]), "=r"((r)[18]), "=r"((r)[19]), \
          "=r"((r)[20]), "=r"((r)[21]), "=r"((r)[22]), "=r"((r)[23]), \
          "=r"((r)[24]), "=r"((r)[25]), "=r"((r)[26]), "=r"((r)[27]), \
          "=r"((r)[28]), "=r"((r)[29]), "=r"((r)[30]), "=r"((r)[31]) \
        : "r"(addr))

// one K=64 bf16 pass = 4 MMAs of K=16
__device__ __forceinline__ void mma4(uint32_t d, uint32_t a_s, uint32_t b_s, uint32_t en0) {
    uint64_t ad = DESC_SW128 | ((uint64_t)(a_s >> 4) & 0x3FFF);
    uint64_t bd = DESC_SW128 | ((uint64_t)(b_s >> 4) & 0x3FFF);
#pragma unroll
    for (int k = 0; k < 4; k++) {
        uint32_t en = (k > 0) ? 1u : en0;
        asm volatile(
            "{\n\t.reg .pred p;\n\tsetp.ne.u32 p, %4, 0;\n\t"
            "tcgen05.mma.cta_group::1.kind::f16 [%0], %1, %2, %3, {%5, %5, %5, %5}, p;\n\t}"
            :: "r"(d), "l"(ad + 2 * k), "l"(bd + 2 * k), "r"(IDESC_BF16), "r"(en), "r"(0u)
            : "memory");
    }
}
// bf16-split GEMM: D = Ah*Bh + Al*Bh + Ah*Bl
__device__ __forceinline__ void gemm3(uint32_t d, uint32_t ah, uint32_t al,
                                      uint32_t bh, uint32_t bl) {
    mma4(d, ah, bh, 0);
    mma4(d, al, bh, 1);
    mma4(d, ah, bl, 1);
}
#endif

__global__ void __launch_bounds__(256, 2)
warped_kernel(const float* __restrict__ x, float* __restrict__ y) {
#if defined(__CUDA_ARCH_FEAT_SM103_ALL)
    extern __shared__ char sm[];
    const uint32_t sb = smem_u32(sm);
    const int tid = threadIdx.x;
    const int lane = tid & 31;
    const int w = tid >> 5;                // 0..7
    const int mg = (w & 3) * 32 + lane;    // TMEM lane (subpartition = w%4)
    const int cbg = (w >> 2) * 32;         // 32-col half for 8-warp epilogues
    const uint32_t MB = sb + SM_MBAR;

    if (w == 0) TCGEN05_ALLOC(sb + SM_TPTR, 128);
    if (tid == 0) MBARRIER_INIT(MB, 1);
    if (tid < 64) {
        float q = (float)(2 * tid + 1);
        *(float*)(sm + SM_S64 + tid * 4) =
            sinpif(63.0f * q * (1.0f / 128.0f)) / (64.0f * sinpif(q * (1.0f / 128.0f)));
    }
    __syncthreads();
    uint32_t tb;
    asm volatile("ld.shared.b32 %0, [%1];" : "=r"(tb) : "r"(sb + SM_TPTR));
    const uint32_t D0 = tb, D1 = tb + 64;

    // circulants hi/lo: Bu[j][k]=s[(j-k)&63], Bd[j][k]=s[(j-k-1)&63]
    {
        const float* s64 = (const float*)(sm + SM_S64);
#pragma unroll
        for (int i = 0; i < 16; i++) {
            int idx = tid + 256 * i;
            int j = idx >> 6, k = idx & 63;
            uint32_t o = amap16(j, k);
            float su = s64[(j - k) & 63];
            float sd = s64[(j - k - 1) & 63];
            __nv_bfloat16 h = __float2bfloat16(su);
            *(__nv_bfloat16*)(sm + SM_BUH + o) = h;
            *(__nv_bfloat16*)(sm + SM_BUL + o) = __float2bfloat16(su - __bfloat162float(h));
            h = __float2bfloat16(sd);
            *(__nv_bfloat16*)(sm + SM_BDH + o) = h;
            *(__nv_bfloat16*)(sm + SM_BDL + o) = __float2bfloat16(sd - __bfloat162float(h));
        }
    }

    // load 2 images: x row-form -> S0, xT -> S1 (packed hi/lo)
    const float4* xg = (const float4*)(x + (size_t)blockIdx.x * 8192);
#pragma unroll
    for (int i = 0; i < 8; i++) {
        int f = tid + 256 * i;
        int mr = f >> 4, c4 = (f & 15) << 2;
        float4 v = xg[f];
        uint32_t h01, l01, h23, l23;
        bsplit2(v.x, v.y, h01, l01);
        bsplit2(v.z, v.w, h23, l23);
        uint32_t a0 = amap16(mr, c4), a1 = amap16(mr, c4 + 2);
        *(uint32_t*)(sm + SM_S0H + a0) = h01;
        *(uint32_t*)(sm + SM_S0L + a0) = l01;
        *(uint32_t*)(sm + SM_S0H + a1) = h23;
        *(uint32_t*)(sm + SM_S0L + a1) = l23;
        int rowb = (mr >= 64) ? 64 : 0, colr = mr & 63;
        uint32_t t0 = amap16(rowb + c4 + 0, colr), t1 = amap16(rowb + c4 + 1, colr);
        uint32_t t2 = amap16(rowb + c4 + 2, colr), t3 = amap16(rowb + c4 + 3, colr);
        *(uint16_t*)(sm + SM_S1H + t0) = (uint16_t)h01;
        *(uint16_t*)(sm + SM_S1L + t0) = (uint16_t)l01;
        *(uint16_t*)(sm + SM_S1H + t1) = (uint16_t)(h01 >> 16);
        *(uint16_t*)(sm + SM_S1L + t1) = (uint16_t)(l01 >> 16);
        *(uint16_t*)(sm + SM_S1H + t2) = (uint16_t)h23;
        *(uint16_t*)(sm + SM_S1L + t2) = (uint16_t)l23;
        *(uint16_t*)(sm + SM_S1H + t3) = (uint16_t)(h23 >> 16);
        *(uint16_t*)(sm + SM_S1L + t3) = (uint16_t)(l23 >> 16);
    }
    FENCE_PROXY_ASYNC();
    __syncthreads();

    int ph = 0;
    float* ycta = y + (size_t)blockIdx.x * 8192;

    // G1: D0 = x*Su ; G3: D1 = xT*Su (merged commit)
    if (w == 0 && elect1()) {
        gemm3(D0, sb + SM_S0H, sb + SM_S0L, sb + SM_BUH, sb + SM_BUL);
        gemm3(D1, sb + SM_S1H, sb + SM_S1L, sb + SM_BUH, sb + SM_BUL);
        TCGEN05_COMMIT(MB);
    }
    MBARRIER_WAIT_PARITY(MB, ph); ph ^= 1;
    TCGEN05_FENCE_AFTER();

    // E1 (8 warps, 32 cols): a01 = silu(D0) -> S1 (xT dead)
    {
        uint32_t r[32];
        LDTM_X32(r, D0 + cbg);
        TCGEN05_WAIT_LD();
#pragma unroll
        for (int t = 0; t < 16; t++) {
            float v0 = silu_f(__uint_as_float(r[2 * t]));
            float v1 = silu_f(__uint_as_float(r[2 * t + 1]));
            uint32_t h2, l2;
            bsplit2(v0, v1, h2, l2);
            uint32_t a = amap16(mg, cbg + 2 * t);
            *(uint32_t*)(sm + SM_S1H + a) = h2;
            *(uint32_t*)(sm + SM_S1L + a) = l2;
        }
    }
    TCGEN05_FENCE_BEFORE();
    FENCE_PROXY_ASYNC();
    __syncthreads();

    // G2: D0 = a01*Sd
    if (w == 0 && elect1()) {
        gemm3(D0, sb + SM_S1H, sb + SM_S1L, sb + SM_BDH, sb + SM_BDL);
        TCGEN05_COMMIT(MB);
    }
    MBARRIER_WAIT_PARITY(MB, ph); ph ^= 1;
    TCGEN05_FENCE_AFTER();

    if (w < 4) {
        // E2 (4 warps, 64 cols): y = 0.25*(silu(x) + D0) -> global
        int img = (mg >= 64) ? 1 : 0;
        float* yg = ycta + img * 4096 + (mg & 63) * 64;
#pragma unroll
        for (int hblk = 0; hblk < 2; hblk++) {
            uint32_t r[32];
            LDTM_X32(r, D0 + 32 * hblk);
            TCGEN05_WAIT_LD();
#pragma unroll
            for (int t = 0; t < 16; t++) {
                uint32_t a = amap16(mg, 32 * hblk + 2 * t);
                uint32_t xh = *(const uint32_t*)(sm + SM_S0H + a);
                uint32_t xl = *(const uint32_t*)(sm + SM_S0L + a);
                float2 o;
                o.x = 0.25f * (silu_f(bjoin2(xh, xl, 0)) + __uint_as_float(r[2 * t]));
                o.y = 0.25f * (silu_f(bjoin2(xh, xl, 1)) + __uint_as_float(r[2 * t + 1]));
                *(float2*)(yg + 32 * hblk + 2 * t) = o;
            }
        }
        TCGEN05_FENCE_BEFORE();
    } else {
        // E3 (4 warps): de-transpose D1 (x10^T) -> S1 (a01 dead: G2 completed)
        int img64 = (mg >= 64) ? 64 : 0, colm = mg & 63;
#pragma unroll
        for (int hblk = 0; hblk < 2; hblk++) {
            uint32_t r[32];
            LDTM_X32(r, D1 + 32 * hblk);
            TCGEN05_WAIT_LD();
#pragma unroll
            for (int t = 0; t < 16; t++) {
                uint32_t h2, l2;
                bsplit2(__uint_as_float(r[2 * t]), __uint_as_float(r[2 * t + 1]), h2, l2);
                uint32_t a0 = amap16(img64 + 32 * hblk + 2 * t, colm);
                uint32_t a1 = amap16(img64 + 32 * hblk + 2 * t + 1, colm);
                *(uint16_t*)(sm + SM_S1H + a0) = (uint16_t)h2;
                *(uint16_t*)(sm + SM_S1L + a0) = (uint16_t)l2;
                *(uint16_t*)(sm + SM_S1H + a1) = (uint16_t)(h2 >> 16);
                *(uint16_t*)(sm + SM_S1L + a1) = (uint16_t)(l2 >> 16);
            }
        }
        TCGEN05_FENCE_BEFORE();
        FENCE_PROXY_ASYNC();
        HALF_BAR();
        // G4: D1 = x10*Su  (early commit; overlaps E2 tail)
        if (w == 4 && elect1()) {
            gemm3(D1, sb + SM_S1H, sb + SM_S1L, sb + SM_BUH, sb + SM_BUL);
            TCGEN05_COMMIT(MB);
        }
    }
    MBARRIER_WAIT_PARITY(MB, ph); ph ^= 1;
    TCGEN05_FENCE_AFTER();
    __syncthreads();   // protect S0: E2 readers must pass before E4 writes

    // E4 (8 warps, 32 cols): a11 = silu(D1) -> S0 (x dead)
    {
        uint32_t r[32];
        LDTM_X32(r, D1 + cbg);
        TCGEN05_WAIT_LD();
#pragma unroll
        for (int t = 0; t < 16; t++) {
            float v0 = silu_f(__uint_as_float(r[2 * t]));
            float v1 = silu_f(__uint_as_float(r[2 * t + 1]));
            uint32_t h2, l2;
            bsplit2(v0, v1, h2, l2);
            uint32_t a = amap16(mg, cbg + 2 * t);
            *(uint32_t*)(sm + SM_S0H + a) = h2;
            *(uint32_t*)(sm + SM_S0L + a) = l2;
        }
    }
    TCGEN05_FENCE_BEFORE();
    FENCE_PROXY_ASYNC();
    __syncthreads();

    // G5: D0 = a11*Sd
    if (w == 0 && elect1()) {
        gemm3(D0, sb + SM_S0H, sb + SM_S0L, sb + SM_BDH, sb + SM_BDL);
        TCGEN05_COMMIT(MB);
    }
    MBARRIER_WAIT_PARITY(MB, ph); ph ^= 1;
    TCGEN05_FENCE_AFTER();

    // E5 (8 warps): W = D0 + silu(x10 from S1) in regs; then W^T -> S1
    {
        uint32_t r[32];
        LDTM_X32(r, D0 + cbg);
        TCGEN05_WAIT_LD();
#pragma unroll
        for (int t = 0; t < 16; t++) {
            uint32_t a = amap16(mg, cbg + 2 * t);
            uint32_t xh = *(const uint32_t*)(sm + SM_S1H + a);
            uint32_t xl = *(const uint32_t*)(sm + SM_S1L + a);
            float w0 = __uint_as_float(r[2 * t])     + silu_f(bjoin2(xh, xl, 0));
            float w1 = __uint_as_float(r[2 * t + 1]) + silu_f(bjoin2(xh, xl, 1));
            r[2 * t] = __float_as_uint(w0);
            r[2 * t + 1] = __float_as_uint(w1);
        }
        TCGEN05_FENCE_BEFORE();
        __syncthreads();   // all x10 reads done before overwrite
        int img64 = (mg >= 64) ? 64 : 0, colm = mg & 63;
#pragma unroll
        for (int t = 0; t < 16; t++) {
            uint32_t h2, l2;
            bsplit2(__uint_as_float(r[2 * t]), __uint_as_float(r[2 * t + 1]), h2, l2);
            uint32_t a0 = amap16(img64 + cbg + 2 * t, colm);
            uint32_t a1 = amap16(img64 + cbg + 2 * t + 1, colm);
            *(uint16_t*)(sm + SM_S1H + a0) = (uint16_t)h2;
            *(uint16_t*)(sm + SM_S1L + a0) = (uint16_t)l2;
            *(uint16_t*)(sm + SM_S1H + a1) = (uint16_t)(h2 >> 16);
            *(uint16_t*)(sm + SM_S1L + a1) = (uint16_t)(l2 >> 16);
        }
    }
    FENCE_PROXY_ASYNC();
    __syncthreads();

    // G6: D1 = W^T*Sd  ( = (Su*W)^T )
    if (w == 0 && elect1()) {
        gemm3(D1, sb + SM_S1H, sb + SM_S1L, sb + SM_BDH, sb + SM_BDL);
        TCGEN05_COMMIT(MB);
    }
    MBARRIER_WAIT_PARITY(MB, ph); ph ^= 1;
    TCGEN05_FENCE_AFTER();

    // E6 (8 warps): y += 0.25 * branch2 (global RMW; coalesced 128B segments)
    {
        uint32_t r[32];
        LDTM_X32(r, D1 + cbg);
        TCGEN05_WAIT_LD();
        int img = (mg >= 64) ? 1 : 0, colm = mg & 63;
        float* yg = ycta + img * 4096 + colm;
#pragma unroll
        for (int c = 0; c < 32; c++) {
            float* p = yg + (cbg + c) * 64;
            *p = *p + 0.25f * __uint_as_float(r[c]);
        }
    }
    TCGEN05_FENCE_BEFORE();
    __syncthreads();
    if (tid == 0) MBARRIER_INVAL(MB);
    __syncthreads();
    if (w == 0) {
        TCGEN05_RELINQ();
        TCGEN05_DEALLOC(tb, 128);
    }

#else
    // ===== compact FFMA fallback (compat PTX pass only; never runs on GB300) =====
#define FS 65
    extern __shared__ float fsm[];
    float* Su = fsm;
    float* Sd = Su + 64 * FS;
    float* bx = Sd + 64 * FS;
    float* t1 = bx + 64 * FS;
    float* t2 = t1 + 64 * FS;
    float* s64 = t2 + 64 * FS;
    const int tid = threadIdx.x;
    if (tid < 64) {
        float q = (float)(2 * tid + 1);
        s64[tid] = sinpif(63.0f * q * (1.0f / 128.0f)) /
                   (64.0f * sinpif(q * (1.0f / 128.0f)));
    }
    __syncthreads();
    for (int idx = tid; idx < 4096; idx += 256) {
        int n = idx >> 6, j = idx & 63;
        Su[n * FS + j] = s64[(j - n) & 63];
        Sd[n * FS + j] = s64[(j - n - 1) & 63];
    }
    __syncthreads();
    for (int img = 0; img < 2; img++) {
        const float* xin = x + ((size_t)blockIdx.x * 2 + img) * 4096;
        float* yout      = y + ((size_t)blockIdx.x * 2 + img) * 4096;
        for (int idx = tid; idx < 4096; idx += 256)
            bx[(idx >> 6) * FS + (idx & 63)] = xin[idx];
        __syncthreads();
        float acc[16];
        for (int e = 0; e < 16; e++) {
            int idx = tid + 256 * e, n = idx >> 6, j = idx & 63;
            float s = 0.f;
            for (int k = 0; k < 64; k++) s = fmaf(bx[n * FS + k], Su[k * FS + j], s);
            t1[n * FS + j] = silu_f(s);
        }
        __syncthreads();
        for (int e = 0; e < 16; e++) {
            int idx = tid + 256 * e, n = idx >> 6, j = idx & 63;
            float s = silu_f(bx[n * FS + j]), u = 0.f;
            for (int k = 0; k < 64; k++) {
                s = fmaf(t1[n * FS + k], Sd[k * FS + j], s);
                u = fmaf(Su[k * FS + n], bx[k * FS + j], u);
            }
            acc[e] = s;
            t2[n * FS + j] = u;
        }
        __syncthreads();
        for (int e = 0; e < 16; e++) {
            int idx = tid + 256 * e, n = idx >> 6, j = idx & 63;
            float s = 0.f;
            for (int k = 0; k < 64; k++) s = fmaf(t2[n * FS + k], Su[k * FS + j], s);
            t1[n * FS + j] = silu_f(s);
        }
        __syncthreads();
        for (int e = 0; e < 16; e++) {
            int idx = tid + 256 * e, n = idx >> 6, j = idx & 63;
            float s = silu_f(t2[n * FS + j]);
            for (int k = 0; k < 64; k++) s = fmaf(t1[n * FS + k], Sd[k * FS + j], s);
            bx[n * FS + j] = s;
        }
        __syncthreads();
        for (int e = 0; e < 16; e++) {
            int idx = tid + 256 * e, n = idx >> 6, j = idx & 63;
            float s = acc[e];
            for (int k = 0; k < 64; k++) s = fmaf(Su[n * FS + k], bx[k * FS + j], s);
            yout[idx] = 0.25f * s;
        }
        __syncthreads();
    }
#endif
}

extern "C" void kernel_launch(void* const* d_in, const int* in_sizes, int n_in,
                              void* d_out, int out_size) {
    const float* x = (const float*)d_in[0];
    float* y = (float*)d_out;
    const int n_img = in_sizes[0] / 4096;      // 2048
    cudaFuncSetAttribute(warped_kernel,
                         cudaFuncAttributeMaxDynamicSharedMemorySize, SM_TOTAL);
    warped_kernel<<<n_img / 2, 256, SM_TOTAL>>>(x, y);
}

// round 11
// speedup vs baseline: 1.2039x; 1.2039x over previous
#include <cuda_runtime.h>
#include <cuda_bf16.h>
#include <cstdint>

// WarpedNonlinearity (math R1; bf16-split numerics R8 @4.1e-6):
//   4*y = silu(x) + silu(x*Su)*Sd + Su*( silu(Su^T*x) + silu((Su^T*x)*Su)*Sd )
// R11: TWO pipelines (A/B, 2 images each) interleaved at stage granularity in ONE
// instruction stream: waitA-epiA-commitA-waitB-epiB-commitB-... so each pipeline's
// MMA flight is covered by the other's epilogue. 16 warps, 4 img/CTA, grid=512.

#define SM_TPTR  0
#define SM_MBAR0 16          // MBA=+16, MBB=+32
#define SM_S64   64
#define SM_BUH   1024
#define SM_BUL   9216
#define SM_BDH   17408
#define SM_BDL   25600
#define SM_CH0   33792
#define CH_SZ    98304
#define P_S0H 0              // x -> R0
#define P_S0L 16384
#define P_S1H 32768          // xT -> a01 -> a11 -> W^T
#define P_S1L 49152
#define P_S2H 65536          // x10
#define P_S2L 81920
#define SM_TOTAL 230400

#define IDESC_BF16 0x8100490u

static constexpr uint64_t DESC_SW128 =
    (uint64_t(2) << 61) | (uint64_t(1) << 46) | (uint64_t(64) << 32) | (uint64_t(1) << 16);

__device__ __forceinline__ float silu_f(float v) {
    return __fdividef(v, 1.0f + __expf(-v));
}

#if defined(__CUDA_ARCH_FEAT_SM103_ALL)
__device__ __forceinline__ uint32_t smem_u32(const void* p) {
    uint32_t a;
    asm("{ .reg .u64 t; cvta.to.shared.u64 t, %1; cvt.u32.u64 %0, t; }" : "=r"(a) : "l"(p));
    return a;
}
__device__ __forceinline__ uint32_t elect1() {
    uint32_t r;
    asm volatile("{ .reg .pred p; elect.sync _|p, 0xFFFFFFFF; selp.b32 %0,1,0,p; }" : "=r"(r));
    return r;
}
__device__ __forceinline__ uint32_t amap16(uint32_t r, uint32_t c) {
    return (r * 128u + 2u * c) ^ ((r & 7u) << 4);
}
__device__ __forceinline__ void bsplit2(float v0, float v1, uint32_t& hi2, uint32_t& lo2) {
    asm("cvt.rn.bf16x2.f32 %0, %1, %2;" : "=r"(hi2) : "f"(v1), "f"(v0));
    float h0 = __uint_as_float(hi2 << 16);
    float h1 = __uint_as_float(hi2 & 0xffff0000u);
    float l0 = v0 - h0, l1 = v1 - h1;
    asm("cvt.rn.bf16x2.f32 %0, %1, %2;" : "=r"(lo2) : "f"(l1), "f"(l0));
}
__device__ __forceinline__ float bjoin2(uint32_t h2, uint32_t l2, int hi_half) {
    uint32_t hb = hi_half ? (h2 & 0xffff0000u) : (h2 << 16);
    uint32_t lb = hi_half ? (l2 & 0xffff0000u) : (l2 << 16);
    return __uint_as_float(hb) + __uint_as_float(lb);
}

#define MBARRIER_INIT(a, n) \
    asm volatile("mbarrier.init.shared.b64 [%0], %1;" :: "r"((uint32_t)(a)), "r"((uint32_t)(n)) : "memory")
#define MBARRIER_INVAL(a) \
    asm volatile("mbarrier.inval.shared.b64 [%0];" :: "r"((uint32_t)(a)) : "memory")
#define MBARRIER_WAIT_PARITY(mb, par) do { \
    uint32_t _m = (uint32_t)(mb), _p = (uint32_t)(par), _d; \
    asm volatile("{\n\t.reg .pred p;\n\t" \
        "mbarrier.try_wait.parity.acquire.cta.shared::cta.b64 p, [%1], %2;\n\t" \
        "selp.b32 %0, 1, 0, p;\n\t}" : "=r"(_d) : "r"(_m), "r"(_p) : "memory"); \
    if (!_d) { \
        asm volatile("{\n\t.reg .pred P1;\n\t" \
            "WL_%=:\n\t" \
            "mbarrier.try_wait.parity.acquire.cta.shared::cta.b64 P1, [%0], %1, 0x989680;\n\t" \
            "@P1 bra.uni WD_%=;\n\tbra.uni WL_%=;\n\tWD_%=:\n\t}" \
            :: "r"(_m), "r"(_p) : "memory"); \
    } } while (0)

#define TCGEN05_ALLOC(a, n) \
    asm volatile("tcgen05.alloc.cta_group::1.sync.aligned.shared::cta.b32 [%0], %1;" \
                 :: "r"((uint32_t)(a)), "r"((uint32_t)(n)) : "memory")
#define TCGEN05_DEALLOC(t, n) \
    asm volatile("tcgen05.dealloc.cta_group::1.sync.aligned.b32 %0, %1;" :: "r"(t), "r"((uint32_t)(n)))
#define TCGEN05_RELINQ() \
    asm volatile("tcgen05.relinquish_alloc_permit.cta_group::1.sync.aligned;")
#define TCGEN05_COMMIT(mb) \
    asm volatile("tcgen05.commit.cta_group::1.mbarrier::arrive::one.shared::cluster.b64 [%0];" \
                 :: "r"((uint32_t)(mb)) : "memory")
#define TCGEN05_WAIT_LD()  asm volatile("tcgen05.wait::ld.sync.aligned;" ::: "memory")
#define TCGEN05_FENCE_BEFORE() asm volatile("tcgen05.fence::before_thread_sync;" ::: "memory")
#define TCGEN05_FENCE_AFTER()  asm volatile("tcgen05.fence::after_thread_sync;" ::: "memory")
#define FENCE_PROXY_ASYNC() asm volatile("fence.proxy.async.shared::cta;" ::: "memory")

#define LDTM_X32(r, addr) \
    asm volatile("tcgen05.ld.sync.aligned.32x32b.x32.b32 " \
        "{%0, %1, %2, %3, %4, %5, %6, %7, %8, %9, %10, %11, %12, %13, %14, %15, " \
        " %16, %17, %18, %19, %20, %21, %22, %23, %24, %25, %26, %27, %28, %29, %30, %31}, [%32];" \
        : "=r"((r)[0]),  "=r"((r)[1]),  "=r"((r)[2]),  "=r"((r)[3]), \
          "=r"((r)[4]),  "=r"((r)[5]),  "=r"((r)[6]),  "=r"((r)[7]), \
          "=r"((r)[8]),  "=r"((r)[9]),  "=r"((r)[10]), "=r"((r)[11]), \
          "=r"((r)[12]), "=r"((r)[13]), "=r"((r)[14]), "=r"((r)[15]), \
          "=r"((r)[16]), "=r"((r)[17]), "=r"((r)[18]), "=r"((r)[19]), \
          "=r"((r)[20]), "=r"((r)[21]), "=r"((r)[22]), "=r"((r)[23]), \
          "=r"((r)[24]), "=r"((r)[25]), "=r"((r)[26]), "=r"((r)[27]), \
          "=r"((r)[28]), "=r"((r)[29]), "=r"((r)[30]), "=r"((r)[31]) \
        : "r"(addr))

#define LDTM_X16(r, addr) \
    asm volatile("tcgen05.ld.sync.aligned.32x32b.x16.b32 " \
        "{%0, %1, %2, %3, %4, %5, %6, %7, %8, %9, %10, %11, %12, %13, %14, %15}, [%16];" \
        : "=r"((r)[0]),  "=r"((r)[1]),  "=r"((r)[2]),  "=r"((r)[3]), \
          "=r"((r)[4]),  "=r"((r)[5]),  "=r"((r)[6]),  "=r"((r)[7]), \
          "=r"((r)[8]),  "=r"((r)[9]),  "=r"((r)[10]), "=r"((r)[11]), \
          "=r"((r)[12]), "=r"((r)[13]), "=r"((r)[14]), "=r"((r)[15]) \
        : "r"(addr))

__device__ __forceinline__ void mma4(uint32_t d, uint32_t a_s, uint32_t b_s, uint32_t en0) {
    uint64_t ad = DESC_SW128 | ((uint64_t)(a_s >> 4) & 0x3FFF);
    uint64_t bd = DESC_SW128 | ((uint64_t)(b_s >> 4) & 0x3FFF);
#pragma unroll
    for (int k = 0; k < 4; k++) {
        uint32_t en = (k > 0) ? 1u : en0;
        asm volatile(
            "{\n\t.reg .pred p;\n\tsetp.ne.u32 p, %4, 0;\n\t"
            "tcgen05.mma.cta_group::1.kind::f16 [%0], %1, %2, %3, {%5, %5, %5, %5}, p;\n\t}"
            :: "r"(d), "l"(ad + 2 * k), "l"(bd + 2 * k), "r"(IDESC_BF16), "r"(en), "r"(0u)
            : "memory");
    }
}
__device__ __forceinline__ void gemm3(uint32_t d, uint32_t ah, uint32_t al,
                                      uint32_t bh, uint32_t bl) {
    mma4(d, ah, bh, 0);
    mma4(d, al, bh, 1);
    mma4(d, ah, bl, 1);
}

// ---- epilogue stages (16 warps; w<8 task1, w>=8 task2) ----
__device__ __forceinline__ void ep_e1e3(char* sm, uint32_t CB,
                                        uint32_t D0, uint32_t D1, int w, int lane) {
    int wl = w & 7;
    int mg = (wl & 3) * 32 + lane;
    int cbg = (wl >> 2) * 32;
    uint32_t r[32];
    if (w < 8) {           // E1: a01 = silu(D0) -> S1
        LDTM_X32(r, D0 + cbg);
        TCGEN05_WAIT_LD();
#pragma unroll
        for (int t = 0; t < 16; t++) {
            uint32_t h2, l2;
            bsplit2(silu_f(__uint_as_float(r[2 * t])),
                    silu_f(__uint_as_float(r[2 * t + 1])), h2, l2);
            uint32_t a = amap16(mg, cbg + 2 * t);
            *(uint32_t*)(sm + CB + P_S1H + a) = h2;
            *(uint32_t*)(sm + CB + P_S1L + a) = l2;
        }
    } else {               // E3: x10 = detrans(D1) -> S2
        LDTM_X32(r, D1 + cbg);
        TCGEN05_WAIT_LD();
        int img64 = (mg >= 64) ? 64 : 0, colm = mg & 63;
#pragma unroll
        for (int t = 0; t < 16; t++) {
            uint32_t h2, l2;
            bsplit2(__uint_as_float(r[2 * t]), __uint_as_float(r[2 * t + 1]), h2, l2);
            uint32_t a0 = amap16(img64 + cbg + 2 * t, colm);
            uint32_t a1 = amap16(img64 + cbg + 2 * t + 1, colm);
            *(uint16_t*)(sm + CB + P_S2H + a0) = (uint16_t)h2;
            *(uint16_t*)(sm + CB + P_S2L + a0) = (uint16_t)l2;
            *(uint16_t*)(sm + CB + P_S2H + a1) = (uint16_t)(h2 >> 16);
            *(uint16_t*)(sm + CB + P_S2L + a1) = (uint16_t)(l2 >> 16);
        }
    }
}

__device__ __forceinline__ void ep_e2e4(char* sm, uint32_t CB,
                                        uint32_t D0, uint32_t D1, int w, int lane) {
    int wl = w & 7;
    int mg = (wl & 3) * 32 + lane;
    int cbg = (wl >> 2) * 32;
    uint32_t r[32];
    if (w < 8) {           // E2: R0 = silu(x) + D0, in place S0
        LDTM_X32(r, D0 + cbg);
        TCGEN05_WAIT_LD();
#pragma unroll
        for (int t = 0; t < 16; t++) {
            uint32_t a = amap16(mg, cbg + 2 * t);
            uint32_t xh = *(const uint32_t*)(sm + CB + P_S0H + a);
            uint32_t xl = *(const uint32_t*)(sm + CB + P_S0L + a);
            float v0 = silu_f(bjoin2(xh, xl, 0)) + __uint_as_float(r[2 * t]);
            float v1 = silu_f(bjoin2(xh, xl, 1)) + __uint_as_float(r[2 * t + 1]);
            uint32_t h2, l2;
            bsplit2(v0, v1, h2, l2);
            *(uint32_t*)(sm + CB + P_S0H + a) = h2;
            *(uint32_t*)(sm + CB + P_S0L + a) = l2;
        }
    } else {               // E4: a11 = silu(D1) -> S1
        LDTM_X32(r, D1 + cbg);
        TCGEN05_WAIT_LD();
#pragma unroll
        for (int t = 0; t < 16; t++) {
            uint32_t h2, l2;
            bsplit2(silu_f(__uint_as_float(r[2 * t])),
                    silu_f(__uint_as_float(r[2 * t + 1])), h2, l2);
            uint32_t a = amap16(mg, cbg + 2 * t);
            *(uint32_t*)(sm + CB + P_S1H + a) = h2;
            *(uint32_t*)(sm + CB + P_S1L + a) = l2;
        }
    }
}

__device__ __forceinline__ void ep_e5(char* sm, uint32_t CB, uint32_t D0, int w, int lane) {
    int mg = (w & 3) * 32 + lane;
    int cb16 = (w >> 2) * 16;          // 16 cols per warp, 16 warps
    uint32_t r[16];
    LDTM_X16(r, D0 + cb16);
    TCGEN05_WAIT_LD();
    int img64 = (mg >= 64) ? 64 : 0, colm = mg & 63;
#pragma unroll
    for (int t = 0; t < 8; t++) {
        uint32_t a = amap16(mg, cb16 + 2 * t);
        uint32_t xh = *(const uint32_t*)(sm + CB + P_S2H + a);
        uint32_t xl = *(const uint32_t*)(sm + CB + P_S2L + a);
        float w0 = __uint_as_float(r[2 * t])     + silu_f(bjoin2(xh, xl, 0));
        float w1 = __uint_as_float(r[2 * t + 1]) + silu_f(bjoin2(xh, xl, 1));
        uint32_t h2, l2;
        bsplit2(w0, w1, h2, l2);
        uint32_t a0 = amap16(img64 + cb16 + 2 * t, colm);
        uint32_t a1 = amap16(img64 + cb16 + 2 * t + 1, colm);
        *(uint16_t*)(sm + CB + P_S1H + a0) = (uint16_t)h2;
        *(uint16_t*)(sm + CB + P_S1L + a0) = (uint16_t)l2;
        *(uint16_t*)(sm + CB + P_S1H + a1) = (uint16_t)(h2 >> 16);
        *(uint16_t*)(sm + CB + P_S1L + a1) = (uint16_t)(l2 >> 16);
    }
}

__device__ __forceinline__ void ep_e6(char* sm, uint32_t CB, uint32_t D1,
                                      float* yp, int w, int lane) {
    int mg = (w & 3) * 32 + lane;
    int cb16 = (w >> 2) * 16;
    uint32_t r[16];
    LDTM_X16(r, D1 + cb16);
    TCGEN05_WAIT_LD();
    int img = (mg >= 64) ? 1 : 0, colm = mg & 63;
    float* yg = yp + img * 4096 + colm;
#pragma unroll
    for (int c = 0; c < 16; c++) {
        int j = cb16 + c;
        uint32_t a = amap16(img * 64 + j, colm);
        float r0 = bjoin2((uint32_t)*(const uint16_t*)(sm + CB + P_S0H + a) << 16,
                          (uint32_t)*(const uint16_t*)(sm + CB + P_S0L + a) << 16, 1);
        yg[j * 64] = 0.25f * (__uint_as_float(r[c]) + r0);
    }
}
#endif

__global__ void __launch_bounds__(512, 1)
warped_kernel(const float* __restrict__ x, float* __restrict__ y) {
#if defined(__CUDA_ARCH_FEAT_SM103_ALL)
    extern __shared__ char sm[];
    const uint32_t sb = smem_u32(sm);
    const int tid = threadIdx.x;
    const int lane = tid & 31;
    const int w = tid >> 5;
    const uint32_t CBA = SM_CH0, CBB = SM_CH0 + CH_SZ;
    const uint32_t MBA = sb + SM_MBAR0, MBB = sb + SM_MBAR0 + 16;

    if (w == 0) TCGEN05_ALLOC(sb + SM_TPTR, 256);
    if (tid == 0) { MBARRIER_INIT(MBA, 1); MBARRIER_INIT(MBB, 1); }
    if (tid < 64) {
        float q = (float)(2 * tid + 1);
        *(float*)(sm + SM_S64 + tid * 4) =
            sinpif(63.0f * q * (1.0f / 128.0f)) / (64.0f * sinpif(q * (1.0f / 128.0f)));
    }
    __syncthreads();
    uint32_t tb;
    asm volatile("ld.shared.b32 %0, [%1];" : "=r"(tb) : "r"(sb + SM_TPTR));
    const uint32_t D0A = tb, D1A = tb + 64, D0B = tb + 128, D1B = tb + 192;

    // circulants hi/lo
    {
        const float* s64 = (const float*)(sm + SM_S64);
#pragma unroll
        for (int i = 0; i < 8; i++) {
            int idx = tid + 512 * i;
            int j = idx >> 6, k = idx & 63;
            uint32_t o = amap16(j, k);
            float su = s64[(j - k) & 63];
            float sd = s64[(j - k - 1) & 63];
            __nv_bfloat16 h = __float2bfloat16(su);
            *(__nv_bfloat16*)(sm + SM_BUH + o) = h;
            *(__nv_bfloat16*)(sm + SM_BUL + o) = __float2bfloat16(su - __bfloat162float(h));
            h = __float2bfloat16(sd);
            *(__nv_bfloat16*)(sm + SM_BDH + o) = h;
            *(__nv_bfloat16*)(sm + SM_BDL + o) = __float2bfloat16(sd - __bfloat162float(h));
        }
    }

    // load 4 images: pipeline = f>>11; x -> S0, xT -> S1
    const float4* xg = (const float4*)(x + (size_t)blockIdx.x * 16384);
#pragma unroll
    for (int i = 0; i < 8; i++) {
        int f = tid + 512 * i;
        uint32_t CB = SM_CH0 + (uint32_t)(f >> 11) * CH_SZ;
        int g = f & 2047;
        int mr = g >> 4, c4 = (g & 15) << 2;
        float4 v = xg[f];
        uint32_t h01, l01, h23, l23;
        bsplit2(v.x, v.y, h01, l01);
        bsplit2(v.z, v.w, h23, l23);
        uint32_t a0 = amap16(mr, c4), a1 = amap16(mr, c4 + 2);
        *(uint32_t*)(sm + CB + P_S0H + a0) = h01;
        *(uint32_t*)(sm + CB + P_S0L + a0) = l01;
        *(uint32_t*)(sm + CB + P_S0H + a1) = h23;
        *(uint32_t*)(sm + CB + P_S0L + a1) = l23;
        int rowb = (mr >= 64) ? 64 : 0, colr = mr & 63;
        uint32_t t0 = amap16(rowb + c4 + 0, colr), t1 = amap16(rowb + c4 + 1, colr);
        uint32_t t2 = amap16(rowb + c4 + 2, colr), t3 = amap16(rowb + c4 + 3, colr);
        *(uint16_t*)(sm + CB + P_S1H + t0) = (uint16_t)h01;
        *(uint16_t*)(sm + CB + P_S1L + t0) = (uint16_t)l01;
        *(uint16_t*)(sm + CB + P_S1H + t1) = (uint16_t)(h01 >> 16);
        *(uint16_t*)(sm + CB + P_S1L + t1) = (uint16_t)(l01 >> 16);
        *(uint16_t*)(sm + CB + P_S1H + t2) = (uint16_t)h23;
        *(uint16_t*)(sm + CB + P_S1L + t2) = (uint16_t)l23;
        *(uint16_t*)(sm + CB + P_S1H + t3) = (uint16_t)(h23 >> 16);
        *(uint16_t*)(sm + CB + P_S1L + t3) = (uint16_t)(l23 >> 16);
    }
    FENCE_PROXY_ASYNC();
    __syncthreads();

    int phA = 0, phB = 0;
    // stage1: G1/G3 for both pipelines
    if (w == 0 && elect1()) {
        gemm3(D0A, sb + CBA + P_S0H, sb + CBA + P_S0L, sb + SM_BUH, sb + SM_BUL);
        gemm3(D1A, sb + CBA + P_S1H, sb + CBA + P_S1L, sb + SM_BUH, sb + SM_BUL);
        TCGEN05_COMMIT(MBA);
        gemm3(D0B, sb + CBB + P_S0H, sb + CBB + P_S0L, sb + SM_BUH, sb + SM_BUL);
        gemm3(D1B, sb + CBB + P_S1H, sb + CBB + P_S1L, sb + SM_BUH, sb + SM_BUL);
        TCGEN05_COMMIT(MBB);
    }

    // stage2-A: E1/E3 -> G2(a01*Sd), G4(x10*Su)
    MBARRIER_WAIT_PARITY(MBA, phA); phA ^= 1;
    TCGEN05_FENCE_AFTER();
    ep_e1e3(sm, CBA, D0A, D1A, w, lane);
    TCGEN05_FENCE_BEFORE(); FENCE_PROXY_ASYNC(); __syncthreads();
    if (w == 0 && elect1()) {
        gemm3(D0A, sb + CBA + P_S1H, sb + CBA + P_S1L, sb + SM_BDH, sb + SM_BDL);
        gemm3(D1A, sb + CBA + P_S2H, sb + CBA + P_S2L, sb + SM_BUH, sb + SM_BUL);
        TCGEN05_COMMIT(MBA);
    }
    // stage2-B
    MBARRIER_WAIT_PARITY(MBB, phB); phB ^= 1;
    TCGEN05_FENCE_AFTER();
    ep_e1e3(sm, CBB, D0B, D1B, w, lane);
    TCGEN05_FENCE_BEFORE(); FENCE_PROXY_ASYNC(); __syncthreads();
    if (w == 0 && elect1()) {
        gemm3(D0B, sb + CBB + P_S1H, sb + CBB + P_S1L, sb + SM_BDH, sb + SM_BDL);
        gemm3(D1B, sb + CBB + P_S2H, sb + CBB + P_S2L, sb + SM_BUH, sb + SM_BUL);
        TCGEN05_COMMIT(MBB);
    }

    // stage3-A: E2/E4 -> G5(a11*Sd)
    MBARRIER_WAIT_PARITY(MBA, phA); phA ^= 1;
    TCGEN05_FENCE_AFTER();
    ep_e2e4(sm, CBA, D0A, D1A, w, lane);
    TCGEN05_FENCE_BEFORE(); FENCE_PROXY_ASYNC(); __syncthreads();
    if (w == 0 && elect1()) {
        gemm3(D0A, sb + CBA + P_S1H, sb + CBA + P_S1L, sb + SM_BDH, sb + SM_BDL);
        TCGEN05_COMMIT(MBA);
    }
    // stage3-B
    MBARRIER_WAIT_PARITY(MBB, phB); phB ^= 1;
    TCGEN05_FENCE_AFTER();
    ep_e2e4(sm, CBB, D0B, D1B, w, lane);
    TCGEN05_FENCE_BEFORE(); FENCE_PROXY_ASYNC(); __syncthreads();
    if (w == 0 && elect1()) {
        gemm3(D0B, sb + CBB + P_S1H, sb + CBB + P_S1L, sb + SM_BDH, sb + SM_BDL);
        TCGEN05_COMMIT(MBB);
    }

    // stage4-A: E5 (W = D0 + silu(x10); W^T -> S1) -> G6(W^T*Sd)
    MBARRIER_WAIT_PARITY(MBA, phA); phA ^= 1;
    TCGEN05_FENCE_AFTER();
    ep_e5(sm, CBA, D0A, w, lane);
    TCGEN05_FENCE_BEFORE(); FENCE_PROXY_ASYNC(); __syncthreads();
    if (w == 0 && elect1()) {
        gemm3(D1A, sb + CBA + P_S1H, sb + CBA + P_S1L, sb + SM_BDH, sb + SM_BDL);
        TCGEN05_COMMIT(MBA);
    }
    // stage4-B
    MBARRIER_WAIT_PARITY(MBB, phB); phB ^= 1;
    TCGEN05_FENCE_AFTER();
    ep_e5(sm, CBB, D0B, w, lane);
    TCGEN05_FENCE_BEFORE(); FENCE_PROXY_ASYNC(); __syncthreads();
    if (w == 0 && elect1()) {
        gemm3(D1B, sb + CBB + P_S1H, sb + CBB + P_S1L, sb + SM_BDH, sb + SM_BDL);
        TCGEN05_COMMIT(MBB);
    }

    // stage5: E6 writes
    float* yA = y + (size_t)blockIdx.x * 16384;
    MBARRIER_WAIT_PARITY(MBA, phA); phA ^= 1;
    TCGEN05_FENCE_AFTER();
    ep_e6(sm, CBA, D1A, yA, w, lane);
    MBARRIER_WAIT_PARITY(MBB, phB); phB ^= 1;
    TCGEN05_FENCE_AFTER();
    ep_e6(sm, CBB, D1B, yA + 8192, w, lane);

    TCGEN05_FENCE_BEFORE();
    __syncthreads();
    if (tid == 0) { MBARRIER_INVAL(MBA); MBARRIER_INVAL(MBB); }
    __syncthreads();
    if (w == 0) {
        TCGEN05_RELINQ();
        TCGEN05_DEALLOC(tb, 256);
    }

#else
    // ===== compact FFMA fallback (compat PTX pass only; never runs on GB300) =====
#define FS 65
    extern __shared__ float fsm[];
    float* Su = fsm;
    float* Sd = Su + 64 * FS;
    float* bx = Sd + 64 * FS;
    float* t1 = bx + 64 * FS;
    float* t2 = t1 + 64 * FS;
    float* s64 = t2 + 64 * FS;
    const int tid = threadIdx.x;
    if (tid < 64) {
        float q = (float)(2 * tid + 1);
        s64[tid] = sinpif(63.0f * q * (1.0f / 128.0f)) /
                   (64.0f * sinpif(q * (1.0f / 128.0f)));
    }
    __syncthreads();
    for (int idx = tid; idx < 4096; idx += 512) {
        int n = idx >> 6, j = idx & 63;
        Su[n * FS + j] = s64[(j - n) & 63];
        Sd[n * FS + j] = s64[(j - n - 1) & 63];
    }
    __syncthreads();
    for (int img = 0; img < 4; img++) {
        const float* xin = x + ((size_t)blockIdx.x * 4 + img) * 4096;
        float* yout      = y + ((size_t)blockIdx.x * 4 + img) * 4096;
        for (int idx = tid; idx < 4096; idx += 512)
            bx[(idx >> 6) * FS + (idx & 63)] = xin[idx];
        __syncthreads();
        float acc[8];
        for (int e = 0; e < 8; e++) {
            int idx = tid + 512 * e, n = idx >> 6, j = idx & 63;
            float s = 0.f;
            for (int k = 0; k < 64; k++) s = fmaf(bx[n * FS + k], Su[k * FS + j], s);
            t1[n * FS + j] = silu_f(s);
        }
        __syncthreads();
        for (int e = 0; e < 8; e++) {
            int idx = tid + 512 * e, n = idx >> 6, j = idx & 63;
            float s = silu_f(bx[n * FS + j]), u = 0.f;
            for (int k = 0; k < 64; k++) {
                s = fmaf(t1[n * FS + k], Sd[k * FS + j], s);
                u = fmaf(Su[k * FS + n], bx[k * FS + j], u);
            }
            acc[e] = s;
            t2[n * FS + j] = u;
        }
        __syncthreads();
        for (int e = 0; e < 8; e++) {
            int idx = tid + 512 * e, n = idx >> 6, j = idx & 63;
            float s = 0.f;
            for (int k = 0; k < 64; k++) s = fmaf(t2[n * FS + k], Su[k * FS + j], s);
            t1[n * FS + j] = silu_f(s);
        }
        __syncthreads();
        for (int e = 0; e < 8; e++) {
            int idx = tid + 512 * e, n = idx >> 6, j = idx & 63;
            float s = silu_f(t2[n * FS + j]);
            for (int k = 0; k < 64; k++) s = fmaf(t1[n * FS + k], Sd[k * FS + j], s);
            bx[n * FS + j] = s;
        }
        __syncthreads();
        for (int e = 0; e < 8; e++) {
            int idx = tid + 512 * e, n = idx >> 6, j = idx & 63;
            float s = acc[e];
            for (int k = 0; k < 64; k++) s = fmaf(Su[n * FS + k], bx[k * FS + j], s);
            yout[idx] = 0.25f * s;
        }
        __syncthreads();
    }
#endif
}

extern "C" void kernel_launch(void* const* d_in, const int* in_sizes, int n_in,
                              void* d_out, int out_size) {
    const float* x = (const float*)d_in[0];
    float* y = (float*)d_out;
    const int n_img = in_sizes[0] / 4096;      // 2048
    cudaFuncSetAttribute(warped_kernel,
                         cudaFuncAttributeMaxDynamicSharedMemorySize, SM_TOTAL);
    warped_kernel<<<n_img / 4, 512, SM_TOTAL>>>(x, y);
}